// round 2
// baseline (speedup 1.0000x reference)
#include <cuda_runtime.h>
#include <math.h>
#include <math_constants.h>

#define B_   32
#define V_   2048
#define K_   40
#define KP1  41
#define FIN  64
#define D_   4
#define P_   64
#define FILT 128
#define N_   (B_ * V_)
#define QPB  8

// ---- scratch (static device arrays: no allocation allowed) ----
__device__ float g_coords[N_ * 4];                  // 1 MB
__device__ float g_feats[(size_t)N_ * FIN];         // 16 MB
__device__ float g_coll[(size_t)N_ * 2 * P_];       // 32 MB

// ============================================================
// Kernel 1: coords = x@W_s + b_s ; feats = x@W_f + b_f
// block (64,4): 4 rows per block, one output column per thread
// ============================================================
__global__ void __launch_bounds__(256) k_transform(
    const float* __restrict__ x,
    const float* __restrict__ Ws, const float* __restrict__ bs,
    const float* __restrict__ Wf, const float* __restrict__ bf)
{
    __shared__ float xs[4][FIN];
    int row = blockIdx.x * 4 + threadIdx.y;
    int c = threadIdx.x;
    xs[threadIdx.y][c] = x[(size_t)row * FIN + c];
    __syncthreads();

    float acc = 0.f;
    #pragma unroll
    for (int k = 0; k < FIN; k++)
        acc = fmaf(xs[threadIdx.y][k], Wf[k * P_ + c], acc);
    g_feats[(size_t)row * FIN + c] = acc + bf[c];

    if (c < D_) {
        float a2 = 0.f;
        #pragma unroll
        for (int k = 0; k < FIN; k++)
            a2 = fmaf(xs[threadIdx.y][k], Ws[k * D_ + c], a2);
        g_coords[row * 4 + c] = a2 + bs[c];
    }
}

// ============================================================
// Kernel 2: exact KNN (top-41 smallest d2 with lax.top_k tie-break,
// drop global min) + Gaussian-weighted feature max/mean pooling.
// One warp per query. d2 keys kept in registers (64/lane).
// ============================================================
__device__ __forceinline__ unsigned keyof(float d2) {
    unsigned u = __float_as_uint(d2);
    // monotonic float->uint map (handles potential tiny negative d2)
    u ^= (u & 0x80000000u) ? 0xFFFFFFFFu : 0x80000000u;
    return u;
}

__device__ __forceinline__ unsigned long long ullmin_(unsigned long long a, unsigned long long b) {
    return a < b ? a : b;
}

__global__ void __launch_bounds__(256, 2) k_knn()
{
    __shared__ float4 sc[V_];               // 32 KB: batch coords
    __shared__ float  ssq[V_];              // 8 KB : squared norms
    __shared__ int    s_idx[QPB][KP1 + 7];
    __shared__ float  s_w[QPB][KP1 + 7];
    __shared__ int    s_cnt[QPB];

    const int b   = blockIdx.y;
    const int tid = threadIdx.x;
    const float4* cg = reinterpret_cast<const float4*>(g_coords) + (size_t)b * V_;
    for (int t = tid; t < V_; t += 256) {
        float4 c = cg[t];
        sc[t]  = c;
        float s = c.x * c.x;
        s = fmaf(c.y, c.y, s); s = fmaf(c.z, c.z, s); s = fmaf(c.w, c.w, s);
        ssq[t] = s;
    }
    __syncthreads();

    const int w    = tid >> 5;
    const int lane = tid & 31;
    const int q    = blockIdx.x * QPB + w;

    const float4 qc  = sc[q];
    const float  qsq = ssq[q];

    // ---- distance keys (same sq+sq-2*dot form as reference selection) ----
    unsigned key[64];
    #pragma unroll
    for (int j = 0; j < 64; j++) {
        int idx = j * 32 + lane;
        float4 c = sc[idx];
        float dot = qc.x * c.x;
        dot = fmaf(qc.y, c.y, dot);
        dot = fmaf(qc.z, c.z, dot);
        dot = fmaf(qc.w, c.w, dot);
        float d2 = qsq + ssq[idx] - 2.f * dot;
        key[j] = keyof(d2);
    }

    // ---- per-lane two smallest -> tight binary-search bounds ----
    unsigned m1 = 0xFFFFFFFFu, m2 = 0xFFFFFFFFu;
    #pragma unroll
    for (int j = 0; j < 64; j++) {
        unsigned u = key[j];
        unsigned nm1 = min(m1, u);
        unsigned nm2 = min(m2, max(m1, u));
        m1 = nm1; m2 = nm2;
    }
    unsigned lo = m1, hi = m2;
    #pragma unroll
    for (int o = 16; o; o >>= 1) {
        lo = min(lo, __shfl_xor_sync(0xffffffffu, lo, o));
        hi = max(hi, __shfl_xor_sync(0xffffffffu, hi, o));
    }
    // invariant: cnt(<=lo-1) < 41  (lo = global min),  cnt(<=hi) >= 64 >= 41

    // ---- binary search smallest T with cnt(<=T) >= 41 ----
    unsigned T = 0;
    bool found = false;
    while (lo < hi) {
        unsigned mid = lo + ((hi - lo) >> 1);
        int c = 0;
        #pragma unroll
        for (int j = 0; j < 64; j++) c += (key[j] <= mid) ? 1 : 0;
        #pragma unroll
        for (int o = 16; o; o >>= 1) c += __shfl_xor_sync(0xffffffffu, c, o);
        if (c == KP1) {   // exact: T = max selected key
            unsigned mx = 0;
            #pragma unroll
            for (int j = 0; j < 64; j++) if (key[j] <= mid) mx = max(mx, key[j]);
            #pragma unroll
            for (int o = 16; o; o >>= 1) mx = max(mx, __shfl_xor_sync(0xffffffffu, mx, o));
            T = mx; found = true; break;
        }
        if (c > KP1) hi = mid; else lo = mid + 1;
    }
    if (!found) T = lo;

    // ---- selection flags: all key<T, plus smallest-index elements with key==T ----
    int c_less = 0;
    #pragma unroll
    for (int j = 0; j < 64; j++) c_less += (key[j] < T) ? 1 : 0;
    #pragma unroll
    for (int o = 16; o; o >>= 1) c_less += __shfl_xor_sync(0xffffffffu, c_less, o);
    const int take_eq = KP1 - c_less;

    unsigned long long selmask = 0ull;
    unsigned long long mymin = 0xFFFFFFFFFFFFFFFFull;
    int running = 0;
    const unsigned lanemask_lt = (1u << lane) - 1u;
    #pragma unroll
    for (int j = 0; j < 64; j++) {
        bool eq = (key[j] == T);
        unsigned bal = __ballot_sync(0xffffffffu, eq);
        bool sel = (key[j] < T);
        if (eq) {
            int rank = running + __popc(bal & lanemask_lt);
            sel = sel || (rank < take_eq);
        }
        running += __popc(bal);
        if (sel) {
            selmask |= (1ull << j);
            unsigned long long ck =
                ((unsigned long long)key[j] << 32) | (unsigned)(j * 32 + lane);
            mymin = ullmin_(mymin, ck);
        }
    }
    #pragma unroll
    for (int o = 16; o; o >>= 1)
        mymin = ullmin_(mymin, __shfl_xor_sync(0xffffffffu, mymin, o));
    const int dropidx = (int)(unsigned)(mymin & 0xffffffffull);  // min (key,idx): dropped

    // ---- build neighbor list (order irrelevant for max/mean) ----
    if (lane == 0) s_cnt[w] = 0;
    __syncwarp();
    unsigned long long m = selmask;
    while (m) {
        int j = __ffsll((long long)m) - 1;
        m &= m - 1;
        int idx = j * 32 + lane;
        if (idx != dropidx) {
            int p = atomicAdd(&s_cnt[w], 1);
            float4 c = sc[idx];
            float dx = qc.x - c.x, dy = qc.y - c.y, dz = qc.z - c.z, dw = qc.w - c.w;
            float dist = dx * dx;
            dist = fmaf(dy, dy, dist);
            dist = fmaf(dz, dz, dist);
            dist = fmaf(dw, dw, dist);
            s_idx[w][p] = idx;
            s_w[w][p]   = expf(-fabsf(dist * 10.f));  // reference weight form
        }
    }
    __syncwarp();
    const int cnt = s_cnt[w];   // == 40 by construction

    // ---- weighted max / mean pooling over neighbors ----
    const float* fb = g_feats + (size_t)b * V_ * FIN;
    float mx0 = -CUDART_INF_F, mx1 = -CUDART_INF_F, sm0 = 0.f, sm1 = 0.f;
    for (int n = 0; n < cnt; n++) {
        int   idx = s_idx[w][n];
        float wt  = s_w[w][n];
        float f0 = fb[(size_t)idx * FIN + lane];
        float f1 = fb[(size_t)idx * FIN + 32 + lane];
        float v0 = f0 * wt, v1 = f1 * wt;
        mx0 = fmaxf(mx0, v0); mx1 = fmaxf(mx1, v1);
        sm0 += v0;            sm1 += v1;
    }
    const int grow = b * V_ + q;
    float* o = g_coll + (size_t)grow * (2 * P_);
    o[lane]       = mx0;
    o[32 + lane]  = mx1;
    o[64 + lane]  = sm0 * (1.f / (float)K_);
    o[96 + lane]  = sm1 * (1.f / (float)K_);
}

// ============================================================
// Kernel 3: out = tanh([x | collected] @ W_out + b_out)
// 128x128 block tile, 8x8 per thread, BK=16, K=192
// ============================================================
__global__ void __launch_bounds__(256) k_out(
    const float* __restrict__ x,
    const float* __restrict__ Wout, const float* __restrict__ bout,
    float* __restrict__ out)
{
    __shared__ float As[16 * 132];   // [k][row], padded stride
    __shared__ float Bs[16 * 128];   // [k][n]

    const int tidx = threadIdx.x;
    const int tx = tidx & 15, ty = tidx >> 4;
    const int r0 = blockIdx.x * 128;

    float acc[8][8];
    #pragma unroll
    for (int i = 0; i < 8; i++)
        #pragma unroll
        for (int j = 0; j < 8; j++) acc[i][j] = 0.f;

    for (int kt = 0; kt < 12; kt++) {
        // load A tile (U = [x | collected])
        #pragma unroll
        for (int i = 0; i < 2; i++) {
            int t   = tidx + i * 256;       // 0..511
            int row = t >> 2;               // 0..127
            int kq  = (t & 3) * 4;          // 0,4,8,12
            int gk  = kt * 16 + kq;
            const float* src = (gk < FIN)
                ? (x      + (size_t)(r0 + row) * FIN  + gk)
                : (g_coll + (size_t)(r0 + row) * 128 + (gk - FIN));
            float4 v = *reinterpret_cast<const float4*>(src);
            As[(kq + 0) * 132 + row] = v.x;
            As[(kq + 1) * 132 + row] = v.y;
            As[(kq + 2) * 132 + row] = v.z;
            As[(kq + 3) * 132 + row] = v.w;
        }
        // load B tile (W_out rows kt*16 .. kt*16+15)
        #pragma unroll
        for (int i = 0; i < 2; i++) {
            int t  = tidx + i * 256;
            int kr = t >> 5;                // 0..15
            int n  = (t & 31) * 4;          // 0..124
            *reinterpret_cast<float4*>(&Bs[kr * 128 + n]) =
                *reinterpret_cast<const float4*>(Wout + (size_t)(kt * 16 + kr) * 128 + n);
        }
        __syncthreads();

        #pragma unroll
        for (int k = 0; k < 16; k++) {
            float a[8], bb[8];
            *reinterpret_cast<float4*>(&a[0]) =
                *reinterpret_cast<const float4*>(&As[k * 132 + ty * 8]);
            *reinterpret_cast<float4*>(&a[4]) =
                *reinterpret_cast<const float4*>(&As[k * 132 + ty * 8 + 4]);
            *reinterpret_cast<float4*>(&bb[0]) =
                *reinterpret_cast<const float4*>(&Bs[k * 128 + tx * 8]);
            *reinterpret_cast<float4*>(&bb[4]) =
                *reinterpret_cast<const float4*>(&Bs[k * 128 + tx * 8 + 4]);
            #pragma unroll
            for (int i = 0; i < 8; i++)
                #pragma unroll
                for (int j = 0; j < 8; j++)
                    acc[i][j] = fmaf(a[i], bb[j], acc[i][j]);
        }
        __syncthreads();
    }

    float bias[8];
    *reinterpret_cast<float4*>(&bias[0]) = *reinterpret_cast<const float4*>(&bout[tx * 8]);
    *reinterpret_cast<float4*>(&bias[4]) = *reinterpret_cast<const float4*>(&bout[tx * 8 + 4]);

    #pragma unroll
    for (int i = 0; i < 8; i++) {
        int row = r0 + ty * 8 + i;
        float4 o0, o1;
        o0.x = tanhf(acc[i][0] + bias[0]);
        o0.y = tanhf(acc[i][1] + bias[1]);
        o0.z = tanhf(acc[i][2] + bias[2]);
        o0.w = tanhf(acc[i][3] + bias[3]);
        o1.x = tanhf(acc[i][4] + bias[4]);
        o1.y = tanhf(acc[i][5] + bias[5]);
        o1.z = tanhf(acc[i][6] + bias[6]);
        o1.w = tanhf(acc[i][7] + bias[7]);
        *reinterpret_cast<float4*>(&out[(size_t)row * 128 + tx * 8])     = o0;
        *reinterpret_cast<float4*>(&out[(size_t)row * 128 + tx * 8 + 4]) = o1;
    }
}

// ============================================================
extern "C" void kernel_launch(void* const* d_in, const int* in_sizes, int n_in,
                              void* d_out, int out_size)
{
    const float* x    = (const float*)d_in[0];
    // d_in[1] = row_splits (uniform; reference ignores it via reshape)
    const float* Ws   = (const float*)d_in[2];
    const float* bs   = (const float*)d_in[3];
    const float* Wf   = (const float*)d_in[4];
    const float* bf   = (const float*)d_in[5];
    const float* Wout = (const float*)d_in[6];
    const float* bout = (const float*)d_in[7];
    float* out = (float*)d_out;

    k_transform<<<N_ / 4, dim3(64, 4)>>>(x, Ws, bs, Wf, bf);
    k_knn<<<dim3(V_ / QPB, B_), 256>>>();
    k_out<<<N_ / 128, 256>>>(x, Wout, bout, out);
}

// round 3
// speedup vs baseline: 1.0012x; 1.0012x over previous
#include <cuda_runtime.h>
#include <math.h>
#include <math_constants.h>

#define B_   32
#define V_   2048
#define K_   40
#define KP1  41
#define FIN  64
#define D_   4
#define P_   64
#define FILT 128
#define N_   (B_ * V_)
#define QPB  8

// ---- scratch (static device arrays: no allocation allowed) ----
__device__ float g_coords[N_ * 4];                  // 1 MB
__device__ float g_feats[(size_t)N_ * FIN];         // 16 MB
__device__ float g_coll[(size_t)N_ * 2 * P_];       // 32 MB

// ============================================================
// Kernel 1: coords = x@W_s + b_s ; feats = x@W_f + b_f
// block (64,4): 4 rows per block, one output column per thread
// ============================================================
__global__ void __launch_bounds__(256) k_transform(
    const float* __restrict__ x,
    const float* __restrict__ Ws, const float* __restrict__ bs,
    const float* __restrict__ Wf, const float* __restrict__ bf)
{
    __shared__ float xs[4][FIN];
    int row = blockIdx.x * 4 + threadIdx.y;
    int c = threadIdx.x;
    xs[threadIdx.y][c] = x[(size_t)row * FIN + c];
    __syncthreads();

    float acc = 0.f;
    #pragma unroll
    for (int k = 0; k < FIN; k++)
        acc = fmaf(xs[threadIdx.y][k], Wf[k * P_ + c], acc);
    g_feats[(size_t)row * FIN + c] = acc + bf[c];

    if (c < D_) {
        float a2 = 0.f;
        #pragma unroll
        for (int k = 0; k < FIN; k++)
            a2 = fmaf(xs[threadIdx.y][k], Ws[k * D_ + c], a2);
        g_coords[row * 4 + c] = a2 + bs[c];
    }
}

// ============================================================
// Kernel 2: exact KNN (top-41 smallest d2 with lax.top_k tie-break,
// drop global min) + Gaussian-weighted feature max/mean pooling.
// One warp per query. d2 keys kept in registers (64/lane).
// ============================================================
__device__ __forceinline__ unsigned keyof(float d2) {
    unsigned u = __float_as_uint(d2);
    // monotonic float->uint map (handles potential tiny negative d2)
    u ^= (u & 0x80000000u) ? 0xFFFFFFFFu : 0x80000000u;
    return u;
}

__device__ __forceinline__ unsigned long long ullmin_(unsigned long long a, unsigned long long b) {
    return a < b ? a : b;
}

__global__ void __launch_bounds__(256, 2) k_knn()
{
    __shared__ float4 sc[V_];               // 32 KB: batch coords
    __shared__ float  ssq[V_];              // 8 KB : squared norms
    __shared__ int    s_idx[QPB][KP1 + 7];
    __shared__ float  s_w[QPB][KP1 + 7];
    __shared__ int    s_cnt[QPB];

    const int b   = blockIdx.y;
    const int tid = threadIdx.x;
    const float4* cg = reinterpret_cast<const float4*>(g_coords) + (size_t)b * V_;
    for (int t = tid; t < V_; t += 256) {
        float4 c = cg[t];
        sc[t]  = c;
        float s = c.x * c.x;
        s = fmaf(c.y, c.y, s); s = fmaf(c.z, c.z, s); s = fmaf(c.w, c.w, s);
        ssq[t] = s;
    }
    __syncthreads();

    const int w    = tid >> 5;
    const int lane = tid & 31;
    const int q    = blockIdx.x * QPB + w;

    const float4 qc  = sc[q];
    const float  qsq = ssq[q];

    // ---- distance keys (same sq+sq-2*dot form as reference selection) ----
    unsigned key[64];
    #pragma unroll
    for (int j = 0; j < 64; j++) {
        int idx = j * 32 + lane;
        float4 c = sc[idx];
        float dot = qc.x * c.x;
        dot = fmaf(qc.y, c.y, dot);
        dot = fmaf(qc.z, c.z, dot);
        dot = fmaf(qc.w, c.w, dot);
        float d2 = qsq + ssq[idx] - 2.f * dot;
        key[j] = keyof(d2);
    }

    // ---- per-lane two smallest -> tight binary-search bounds ----
    unsigned m1 = 0xFFFFFFFFu, m2 = 0xFFFFFFFFu;
    #pragma unroll
    for (int j = 0; j < 64; j++) {
        unsigned u = key[j];
        unsigned nm1 = min(m1, u);
        unsigned nm2 = min(m2, max(m1, u));
        m1 = nm1; m2 = nm2;
    }
    unsigned lo = m1, hi = m2;
    #pragma unroll
    for (int o = 16; o; o >>= 1) {
        lo = min(lo, __shfl_xor_sync(0xffffffffu, lo, o));
        hi = max(hi, __shfl_xor_sync(0xffffffffu, hi, o));
    }
    // invariant: cnt(<=lo-1) < 41  (lo = global min),  cnt(<=hi) >= 64 >= 41

    // ---- binary search smallest T with cnt(<=T) >= 41 ----
    unsigned T = 0;
    bool found = false;
    while (lo < hi) {
        unsigned mid = lo + ((hi - lo) >> 1);
        int c = 0;
        #pragma unroll
        for (int j = 0; j < 64; j++) c += (key[j] <= mid) ? 1 : 0;
        #pragma unroll
        for (int o = 16; o; o >>= 1) c += __shfl_xor_sync(0xffffffffu, c, o);
        if (c == KP1) {   // exact: T = max selected key
            unsigned mx = 0;
            #pragma unroll
            for (int j = 0; j < 64; j++) if (key[j] <= mid) mx = max(mx, key[j]);
            #pragma unroll
            for (int o = 16; o; o >>= 1) mx = max(mx, __shfl_xor_sync(0xffffffffu, mx, o));
            T = mx; found = true; break;
        }
        if (c > KP1) hi = mid; else lo = mid + 1;
    }
    if (!found) T = lo;

    // ---- selection flags: all key<T, plus smallest-index elements with key==T ----
    int c_less = 0;
    #pragma unroll
    for (int j = 0; j < 64; j++) c_less += (key[j] < T) ? 1 : 0;
    #pragma unroll
    for (int o = 16; o; o >>= 1) c_less += __shfl_xor_sync(0xffffffffu, c_less, o);
    const int take_eq = KP1 - c_less;

    unsigned long long selmask = 0ull;
    unsigned long long mymin = 0xFFFFFFFFFFFFFFFFull;
    int running = 0;
    const unsigned lanemask_lt = (1u << lane) - 1u;
    #pragma unroll
    for (int j = 0; j < 64; j++) {
        bool eq = (key[j] == T);
        unsigned bal = __ballot_sync(0xffffffffu, eq);
        bool sel = (key[j] < T);
        if (eq) {
            int rank = running + __popc(bal & lanemask_lt);
            sel = sel || (rank < take_eq);
        }
        running += __popc(bal);
        if (sel) {
            selmask |= (1ull << j);
            unsigned long long ck =
                ((unsigned long long)key[j] << 32) | (unsigned)(j * 32 + lane);
            mymin = ullmin_(mymin, ck);
        }
    }
    #pragma unroll
    for (int o = 16; o; o >>= 1)
        mymin = ullmin_(mymin, __shfl_xor_sync(0xffffffffu, mymin, o));
    const int dropidx = (int)(unsigned)(mymin & 0xffffffffull);  // min (key,idx): dropped

    // ---- build neighbor list (order irrelevant for max/mean) ----
    if (lane == 0) s_cnt[w] = 0;
    __syncwarp();
    unsigned long long m = selmask;
    while (m) {
        int j = __ffsll((long long)m) - 1;
        m &= m - 1;
        int idx = j * 32 + lane;
        if (idx != dropidx) {
            int p = atomicAdd(&s_cnt[w], 1);
            float4 c = sc[idx];
            float dx = qc.x - c.x, dy = qc.y - c.y, dz = qc.z - c.z, dw = qc.w - c.w;
            float dist = dx * dx;
            dist = fmaf(dy, dy, dist);
            dist = fmaf(dz, dz, dist);
            dist = fmaf(dw, dw, dist);
            s_idx[w][p] = idx;
            s_w[w][p]   = expf(-fabsf(dist * 10.f));  // reference weight form
        }
    }
    __syncwarp();
    const int cnt = s_cnt[w];   // == 40 by construction

    // ---- weighted max / mean pooling over neighbors ----
    const float* fb = g_feats + (size_t)b * V_ * FIN;
    float mx0 = -CUDART_INF_F, mx1 = -CUDART_INF_F, sm0 = 0.f, sm1 = 0.f;
    for (int n = 0; n < cnt; n++) {
        int   idx = s_idx[w][n];
        float wt  = s_w[w][n];
        float f0 = fb[(size_t)idx * FIN + lane];
        float f1 = fb[(size_t)idx * FIN + 32 + lane];
        float v0 = f0 * wt, v1 = f1 * wt;
        mx0 = fmaxf(mx0, v0); mx1 = fmaxf(mx1, v1);
        sm0 += v0;            sm1 += v1;
    }
    const int grow = b * V_ + q;
    float* o = g_coll + (size_t)grow * (2 * P_);
    o[lane]       = mx0;
    o[32 + lane]  = mx1;
    o[64 + lane]  = sm0 * (1.f / (float)K_);
    o[96 + lane]  = sm1 * (1.f / (float)K_);
}

// ============================================================
// Kernel 3: out = tanh([x | collected] @ W_out + b_out)
// 128x128 block tile, 8x8 per thread, BK=16, K=192
// ============================================================
__global__ void __launch_bounds__(256) k_out(
    const float* __restrict__ x,
    const float* __restrict__ Wout, const float* __restrict__ bout,
    float* __restrict__ out)
{
    __shared__ float As[16 * 132];   // [k][row], padded stride
    __shared__ float Bs[16 * 128];   // [k][n]

    const int tidx = threadIdx.x;
    const int tx = tidx & 15, ty = tidx >> 4;
    const int r0 = blockIdx.x * 128;

    float acc[8][8];
    #pragma unroll
    for (int i = 0; i < 8; i++)
        #pragma unroll
        for (int j = 0; j < 8; j++) acc[i][j] = 0.f;

    for (int kt = 0; kt < 12; kt++) {
        // load A tile (U = [x | collected])
        #pragma unroll
        for (int i = 0; i < 2; i++) {
            int t   = tidx + i * 256;       // 0..511
            int row = t >> 2;               // 0..127
            int kq  = (t & 3) * 4;          // 0,4,8,12
            int gk  = kt * 16 + kq;
            const float* src = (gk < FIN)
                ? (x      + (size_t)(r0 + row) * FIN  + gk)
                : (g_coll + (size_t)(r0 + row) * 128 + (gk - FIN));
            float4 v = *reinterpret_cast<const float4*>(src);
            As[(kq + 0) * 132 + row] = v.x;
            As[(kq + 1) * 132 + row] = v.y;
            As[(kq + 2) * 132 + row] = v.z;
            As[(kq + 3) * 132 + row] = v.w;
        }
        // load B tile (W_out rows kt*16 .. kt*16+15)
        #pragma unroll
        for (int i = 0; i < 2; i++) {
            int t  = tidx + i * 256;
            int kr = t >> 5;                // 0..15
            int n  = (t & 31) * 4;          // 0..124
            *reinterpret_cast<float4*>(&Bs[kr * 128 + n]) =
                *reinterpret_cast<const float4*>(Wout + (size_t)(kt * 16 + kr) * 128 + n);
        }
        __syncthreads();

        #pragma unroll
        for (int k = 0; k < 16; k++) {
            float a[8], bb[8];
            *reinterpret_cast<float4*>(&a[0]) =
                *reinterpret_cast<const float4*>(&As[k * 132 + ty * 8]);
            *reinterpret_cast<float4*>(&a[4]) =
                *reinterpret_cast<const float4*>(&As[k * 132 + ty * 8 + 4]);
            *reinterpret_cast<float4*>(&bb[0]) =
                *reinterpret_cast<const float4*>(&Bs[k * 128 + tx * 8]);
            *reinterpret_cast<float4*>(&bb[4]) =
                *reinterpret_cast<const float4*>(&Bs[k * 128 + tx * 8 + 4]);
            #pragma unroll
            for (int i = 0; i < 8; i++)
                #pragma unroll
                for (int j = 0; j < 8; j++)
                    acc[i][j] = fmaf(a[i], bb[j], acc[i][j]);
        }
        __syncthreads();
    }

    float bias[8];
    *reinterpret_cast<float4*>(&bias[0]) = *reinterpret_cast<const float4*>(&bout[tx * 8]);
    *reinterpret_cast<float4*>(&bias[4]) = *reinterpret_cast<const float4*>(&bout[tx * 8 + 4]);

    #pragma unroll
    for (int i = 0; i < 8; i++) {
        int row = r0 + ty * 8 + i;
        float4 o0, o1;
        o0.x = tanhf(acc[i][0] + bias[0]);
        o0.y = tanhf(acc[i][1] + bias[1]);
        o0.z = tanhf(acc[i][2] + bias[2]);
        o0.w = tanhf(acc[i][3] + bias[3]);
        o1.x = tanhf(acc[i][4] + bias[4]);
        o1.y = tanhf(acc[i][5] + bias[5]);
        o1.z = tanhf(acc[i][6] + bias[6]);
        o1.w = tanhf(acc[i][7] + bias[7]);
        *reinterpret_cast<float4*>(&out[(size_t)row * 128 + tx * 8])     = o0;
        *reinterpret_cast<float4*>(&out[(size_t)row * 128 + tx * 8 + 4]) = o1;
    }
}

// ============================================================
extern "C" void kernel_launch(void* const* d_in, const int* in_sizes, int n_in,
                              void* d_out, int out_size)
{
    const float* x    = (const float*)d_in[0];
    // d_in[1] = row_splits (uniform; reference ignores it via reshape)
    const float* Ws   = (const float*)d_in[2];
    const float* bs   = (const float*)d_in[3];
    const float* Wf   = (const float*)d_in[4];
    const float* bf   = (const float*)d_in[5];
    const float* Wout = (const float*)d_in[6];
    const float* bout = (const float*)d_in[7];
    float* out = (float*)d_out;

    k_transform<<<N_ / 4, dim3(64, 4)>>>(x, Ws, bs, Wf, bf);
    k_knn<<<dim3(V_ / QPB, B_), 256>>>();
    k_out<<<N_ / 128, 256>>>(x, Wout, bout, out);
}